// round 10
// baseline (speedup 1.0000x reference)
#include <cuda_runtime.h>

#define B_CONST 8192
#define D_CONST 4096
#define MARGIN 0.5f
#define THREADS 256

#define QUARTERS 4
#define Q_F4 (D_CONST / 4 / QUARTERS)   // 256 float4 per quarter per row

// Per-(quarter, row) partial sums: .x=abs1 .y=abs2 .z=sq1 .w=sq2
__device__ float4 g_partial[QUARTERS * B_CONST];

__global__ void zero_out_kernel(float* out) {
    out[0] = 0.0f;
}

// Phase-blocked partial reduction. bid = h*8192 + b: all CTAs of phase h run
// (in wave order) before phase h+1, so each phase's working set is the 32MB
// quarter-column {all rows} x quarter h — it fits L2 with 4x headroom, so the
// ~3 touches per row-quarter hit L2 after the compulsory miss.
__global__ __launch_bounds__(THREADS) void triplet_partial_kernel(
    const float* __restrict__ feats,
    const int* __restrict__ idx1,
    const int* __restrict__ idx2)
{
    const int bid = blockIdx.x;
    const int h = bid >> 13;        // quarter index 0..3
    const int b = bid & (B_CONST - 1);
    const int tid = threadIdx.x;

    const int i1 = idx1[b];
    const int i2 = idx2[b];

    const float4* ga = (const float4*)(feats + (long long)b  * D_CONST) + h * Q_F4;
    const float4* g1 = (const float4*)(feats + (long long)i1 * D_CONST) + h * Q_F4;
    const float4* g2 = (const float4*)(feats + (long long)i2 * D_CONST) + h * Q_F4;

    // Q_F4 == THREADS: each thread handles exactly one float4 per stream.
    float4 av = __ldg(ga + tid);
    float4 v1 = __ldg(g1 + tid);
    float4 v2 = __ldg(g2 + tid);

    float s_abs1, s_abs2, s_sq1, s_sq2;
    {
        float d;
        d = av.x - v1.x; s_abs1  = fabsf(d); s_sq1  = d * d;
        d = av.y - v1.y; s_abs1 += fabsf(d); s_sq1  = fmaf(d, d, s_sq1);
        d = av.z - v1.z; s_abs1 += fabsf(d); s_sq1  = fmaf(d, d, s_sq1);
        d = av.w - v1.w; s_abs1 += fabsf(d); s_sq1  = fmaf(d, d, s_sq1);
        d = av.x - v2.x; s_abs2  = fabsf(d); s_sq2  = d * d;
        d = av.y - v2.y; s_abs2 += fabsf(d); s_sq2  = fmaf(d, d, s_sq2);
        d = av.z - v2.z; s_abs2 += fabsf(d); s_sq2  = fmaf(d, d, s_sq2);
        d = av.w - v2.w; s_abs2 += fabsf(d); s_sq2  = fmaf(d, d, s_sq2);
    }

    // warp reduce
    #pragma unroll
    for (int off = 16; off > 0; off >>= 1) {
        s_abs1 += __shfl_down_sync(0xFFFFFFFF, s_abs1, off);
        s_abs2 += __shfl_down_sync(0xFFFFFFFF, s_abs2, off);
        s_sq1  += __shfl_down_sync(0xFFFFFFFF, s_sq1,  off);
        s_sq2  += __shfl_down_sync(0xFFFFFFFF, s_sq2,  off);
    }

    __shared__ float4 warp_sums[THREADS / 32];
    const int wid = tid >> 5;
    const int lid = tid & 31;
    if (lid == 0) warp_sums[wid] = make_float4(s_abs1, s_abs2, s_sq1, s_sq2);
    __syncthreads();

    if (wid == 0) {
        float4 v = (lid < THREADS / 32) ? warp_sums[lid]
                                        : make_float4(0.f, 0.f, 0.f, 0.f);
        #pragma unroll
        for (int off = (THREADS / 64); off > 0; off >>= 1) {
            v.x += __shfl_down_sync(0xFFFFFFFF, v.x, off);
            v.y += __shfl_down_sync(0xFFFFFFFF, v.y, off);
            v.z += __shfl_down_sync(0xFFFFFFFF, v.z, off);
            v.w += __shfl_down_sync(0xFFFFFFFF, v.w, off);
        }
        if (lid == 0) g_partial[bid] = v;   // overwritten every replay; no zeroing needed
    }
}

// Epilogue: combine quarters, apply swap/margin logic, reduce, one atomic per CTA.
__global__ __launch_bounds__(THREADS) void triplet_epilogue_kernel(
    const float* __restrict__ label,
    const int* __restrict__ idx1,
    const int* __restrict__ idx2,
    float* __restrict__ out)
{
    const int b = blockIdx.x * THREADS + threadIdx.x;   // row, grid covers 8192
    const int tid = threadIdx.x;

    float4 v = g_partial[b];
    #pragma unroll
    for (int h = 1; h < QUARTERS; h++) {
        float4 p = g_partial[h * B_CONST + b];
        v.x += p.x; v.y += p.y; v.z += p.z; v.w += p.w;
    }

    const int i1 = idx1[b];
    const int i2 = idx2[b];

    const bool swap = (v.x >= v.y);           // l1_1 >= l1_2
    const float near_sse = swap ? v.w : v.z;
    const float far_sse  = swap ? v.z : v.w;
    const float la = label[b];
    const float l1 = label[i1];
    const float l2 = label[i2];
    const float near_label = swap ? l2 : l1;
    const float far_label  = swap ? l1 : l2;
    const float dfar  = la - far_label;
    const float dnear = la - near_label;
    const float alpha = dfar * dfar - dnear * dnear;
    float loss = near_sse - far_sse + alpha * MARGIN;
    loss = (loss > 0.0f) ? loss : 0.0f;

    // block reduce the per-row losses
    #pragma unroll
    for (int off = 16; off > 0; off >>= 1)
        loss += __shfl_down_sync(0xFFFFFFFF, loss, off);

    __shared__ float warp_loss[THREADS / 32];
    const int wid = tid >> 5;
    const int lid = tid & 31;
    if (lid == 0) warp_loss[wid] = loss;
    __syncthreads();

    if (wid == 0) {
        float s = (lid < THREADS / 32) ? warp_loss[lid] : 0.f;
        #pragma unroll
        for (int off = (THREADS / 64); off > 0; off >>= 1)
            s += __shfl_down_sync(0xFFFFFFFF, s, off);
        if (lid == 0) atomicAdd(out, s);
    }
}

extern "C" void kernel_launch(void* const* d_in, const int* in_sizes, int n_in,
                              void* d_out, int out_size) {
    const float* feats = (const float*)d_in[0];
    const float* label = (const float*)d_in[1];
    const int*   idx1  = (const int*)d_in[2];
    const int*   idx2  = (const int*)d_in[3];
    float* out = (float*)d_out;

    zero_out_kernel<<<1, 1>>>(out);
    triplet_partial_kernel<<<QUARTERS * B_CONST, THREADS>>>(feats, idx1, idx2);
    triplet_epilogue_kernel<<<B_CONST / THREADS, THREADS>>>(label, idx1, idx2, out);
}

// round 11
// speedup vs baseline: 1.4176x; 1.4176x over previous
#include <cuda_runtime.h>

#define B_CONST 8192
#define D_CONST 4096
#define MARGIN 0.5f
#define THREADS 256

// Per-row hinge loss, overwritten every replay (no zeroing needed).
__device__ float g_loss[B_CONST];

__global__ __launch_bounds__(THREADS) void triplet_loss_kernel(
    const float* __restrict__ feats,
    const float* __restrict__ label,
    const int* __restrict__ idx1,
    const int* __restrict__ idx2)
{
    const int b = blockIdx.x;
    const int tid = threadIdx.x;

    const int i1 = idx1[b];
    const int i2 = idx2[b];

    const float4* __restrict__ a  = (const float4*)(feats + (long long)b  * D_CONST);
    const float4* __restrict__ t1 = (const float4*)(feats + (long long)i1 * D_CONST);
    const float4* __restrict__ t2 = (const float4*)(feats + (long long)i2 * D_CONST);

    float s_abs1 = 0.f, s_abs2 = 0.f, s_sq1 = 0.f, s_sq2 = 0.f;

    const int NV = D_CONST / 4;  // 1024 float4s per row
    #pragma unroll
    for (int i = tid; i < NV; i += THREADS) {
        float4 av = __ldg(a + i);
        float4 v1 = __ldg(t1 + i);
        float4 v2 = __ldg(t2 + i);

        float d;
        d = av.x - v1.x; s_abs1 += fabsf(d); s_sq1 = fmaf(d, d, s_sq1);
        d = av.y - v1.y; s_abs1 += fabsf(d); s_sq1 = fmaf(d, d, s_sq1);
        d = av.z - v1.z; s_abs1 += fabsf(d); s_sq1 = fmaf(d, d, s_sq1);
        d = av.w - v1.w; s_abs1 += fabsf(d); s_sq1 = fmaf(d, d, s_sq1);

        d = av.x - v2.x; s_abs2 += fabsf(d); s_sq2 = fmaf(d, d, s_sq2);
        d = av.y - v2.y; s_abs2 += fabsf(d); s_sq2 = fmaf(d, d, s_sq2);
        d = av.z - v2.z; s_abs2 += fabsf(d); s_sq2 = fmaf(d, d, s_sq2);
        d = av.w - v2.w; s_abs2 += fabsf(d); s_sq2 = fmaf(d, d, s_sq2);
    }

    // warp reduce
    #pragma unroll
    for (int off = 16; off > 0; off >>= 1) {
        s_abs1 += __shfl_down_sync(0xFFFFFFFF, s_abs1, off);
        s_abs2 += __shfl_down_sync(0xFFFFFFFF, s_abs2, off);
        s_sq1  += __shfl_down_sync(0xFFFFFFFF, s_sq1,  off);
        s_sq2  += __shfl_down_sync(0xFFFFFFFF, s_sq2,  off);
    }

    __shared__ float4 warp_sums[THREADS / 32];
    const int wid = tid >> 5;
    const int lid = tid & 31;
    if (lid == 0) warp_sums[wid] = make_float4(s_abs1, s_abs2, s_sq1, s_sq2);
    __syncthreads();

    if (wid == 0) {
        float4 v = (lid < THREADS / 32) ? warp_sums[lid]
                                        : make_float4(0.f, 0.f, 0.f, 0.f);
        #pragma unroll
        for (int off = (THREADS / 64); off > 0; off >>= 1) {
            v.x += __shfl_down_sync(0xFFFFFFFF, v.x, off);
            v.y += __shfl_down_sync(0xFFFFFFFF, v.y, off);
            v.z += __shfl_down_sync(0xFFFFFFFF, v.z, off);
            v.w += __shfl_down_sync(0xFFFFFFFF, v.w, off);
        }
        if (lid == 0) {
            const float l1_1 = v.x, l1_2 = v.y, sse1 = v.z, sse2 = v.w;
            const bool swap = (l1_1 >= l1_2);
            const float near_sse = swap ? sse2 : sse1;
            const float far_sse  = swap ? sse1 : sse2;
            const float la = label[b];
            const float l1 = label[i1];
            const float l2 = label[i2];
            const float near_label = swap ? l2 : l1;
            const float far_label  = swap ? l1 : l2;
            const float dfar  = la - far_label;
            const float dnear = la - near_label;
            const float alpha = dfar * dfar - dnear * dnear;
            const float loss = near_sse - far_sse + alpha * MARGIN;
            g_loss[b] = (loss > 0.0f) ? loss : 0.0f;   // overwrite; no atomics, no zeroing
        }
    }
}

// Single-CTA final reduction: sums g_loss[0..8191] and writes out[0] directly.
__global__ __launch_bounds__(1024) void final_reduce_kernel(float* __restrict__ out) {
    const int tid = threadIdx.x;

    // 8192 floats = 2048 float4; 1024 threads x 2 float4 each.
    const float4* p = (const float4*)g_loss;
    float4 x = p[tid];
    float4 y = p[tid + 1024];
    float s = (x.x + x.y) + (x.z + x.w) + (y.x + y.y) + (y.z + y.w);

    #pragma unroll
    for (int off = 16; off > 0; off >>= 1)
        s += __shfl_down_sync(0xFFFFFFFF, s, off);

    __shared__ float warp_sum[32];
    const int wid = tid >> 5;
    const int lid = tid & 31;
    if (lid == 0) warp_sum[wid] = s;
    __syncthreads();

    if (wid == 0) {
        float t = (lid < 32) ? warp_sum[lid] : 0.f;
        #pragma unroll
        for (int off = 16; off > 0; off >>= 1)
            t += __shfl_down_sync(0xFFFFFFFF, t, off);
        if (lid == 0) out[0] = t;
    }
}

extern "C" void kernel_launch(void* const* d_in, const int* in_sizes, int n_in,
                              void* d_out, int out_size) {
    const float* feats = (const float*)d_in[0];
    const float* label = (const float*)d_in[1];
    const int*   idx1  = (const int*)d_in[2];
    const int*   idx2  = (const int*)d_in[3];
    float* out = (float*)d_out;

    triplet_loss_kernel<<<B_CONST, THREADS>>>(feats, label, idx1, idx2);
    final_reduce_kernel<<<1, 1024>>>(out);
}